// round 13
// baseline (speedup 1.0000x reference)
#include <cuda_runtime.h>
#include <cuda_fp16.h>

typedef unsigned int u32;

#define SCALE_F 11.313708498984761f   // sqrt(128)

// ---------------- scratch (all single fp16; gate fp32) ----------------
static __device__ __half g_x[8388608];
static __device__ __half g_wq[4194304], g_wg[4194304], g_wo[4194304];
static __device__ __half g_k[8388608];
static __device__ __half g_vt[8388608];
static __device__ __half g_q[8388608];
static __device__ float  g_gate[8388608];
static __device__ __half g_a[8388608];

// ---------------- helpers ----------------
__device__ __forceinline__ u32 smem_u32(const void* p) {
    u32 a;
    asm("{ .reg .u64 t; cvta.to.shared.u64 t, %1; cvt.u32.u64 %0, t; }" : "=r"(a) : "l"(p));
    return a;
}
#define SWZ(o) ((o) ^ (((o) >> 3) & 0x70))

__device__ __forceinline__ void ldsm4(u32 addr, u32& r0, u32& r1, u32& r2, u32& r3) {
    asm volatile("ldmatrix.sync.aligned.m8n8.x4.shared.b16 {%0,%1,%2,%3}, [%4];"
                 : "=r"(r0), "=r"(r1), "=r"(r2), "=r"(r3) : "r"(addr));
}
__device__ __forceinline__ void mma16816(float (&d)[4], u32 a0, u32 a1, u32 a2, u32 a3,
                                         u32 b0, u32 b1) {
    asm volatile(
        "mma.sync.aligned.m16n8k16.row.col.f32.f16.f16.f32 "
        "{%0,%1,%2,%3},{%4,%5,%6,%7},{%8,%9},{%0,%1,%2,%3};"
        : "+f"(d[0]), "+f"(d[1]), "+f"(d[2]), "+f"(d[3])
        : "r"(a0), "r"(a1), "r"(a2), "r"(a3), "r"(b0), "r"(b1));
}
// fp16-accumulator variant (C/D = 2 x b32 packed halves)
__device__ __forceinline__ void mma16816h(u32 (&d)[2], u32 a0, u32 a1, u32 a2, u32 a3,
                                          u32 b0, u32 b1) {
    asm volatile(
        "mma.sync.aligned.m16n8k16.row.col.f16.f16.f16.f16 "
        "{%0,%1},{%2,%3,%4,%5},{%6,%7},{%0,%1};"
        : "+r"(d[0]), "+r"(d[1])
        : "r"(a0), "r"(a1), "r"(a2), "r"(a3), "r"(b0), "r"(b1));
}
__device__ __forceinline__ void cpasync16(u32 dst, const void* src) {
    asm volatile("cp.async.cg.shared.global [%0], [%1], 16;" :: "r"(dst), "l"(src));
}
#define CP_COMMIT asm volatile("cp.async.commit_group;" ::: "memory")
#define CP_WAIT(n) asm volatile("cp.async.wait_group %0;" :: "n"(n) : "memory")

// silu via tanh.approx: 1 MUFU + 2 fma
__device__ __forceinline__ float silu_f(float x) {
    float h = 0.5f * x;
    float t;
    asm("tanh.approx.f32 %0, %1;" : "=f"(t) : "f"(h));
    return fmaf(h, t, h);
}
// pack two f32 -> f16x2 in one cvt (lo = first arg)
__device__ __forceinline__ u32 cvt2h(float lo, float hi) {
    u32 d;
    asm("cvt.rn.f16x2.f32 %0, %1, %2;" : "=r"(d) : "f"(hi), "f"(lo));
    return d;
}

// ---------------- merged pre-pass: one launch ----------------
__global__ void prep_kernel(const float* __restrict__ x,  __half* __restrict__ dx,
                            const float* __restrict__ kw, __half* __restrict__ dk,
                            const float* __restrict__ wq, __half* __restrict__ dq,
                            const float* __restrict__ wg, __half* __restrict__ dg,
                            const float* __restrict__ wo, __half* __restrict__ dw,
                            const float* __restrict__ vw, __half* __restrict__ dvt) {
    const int y = blockIdx.y;
    if (y == 5) {
        __shared__ float sm[32][33];
        int c0 = (blockIdx.x & 63) * 32;
        int m0 = (blockIdx.x >> 6) * 32;
        int tx = threadIdx.x & 31, ty = threadIdx.x >> 5;
#pragma unroll
        for (int j = 0; j < 4; j++)
            sm[ty + 8 * j][tx] = vw[(size_t)(m0 + ty + 8 * j) * 2048 + c0 + tx] * SCALE_F;
        __syncthreads();
#pragma unroll
        for (int j = 0; j < 4; j++)
            dvt[(size_t)(c0 + ty + 8 * j) * 4096 + m0 + tx] = __float2half_rn(sm[tx][ty + 8 * j]);
        return;
    }
    int i = blockIdx.x * blockDim.x + threadIdx.x;
    const float* s;
    __half* d;
    float scale = 1.0f;
    int n4;
    if (y == 0)      { s = x;  d = dx; n4 = 2097152; }
    else if (y == 1) { s = kw; d = dk; n4 = 2097152; scale = SCALE_F; }
    else if (y == 2) { s = wq; d = dq; n4 = 1048576; }
    else if (y == 3) { s = wg; d = dg; n4 = 1048576; }
    else             { s = wo; d = dw; n4 = 1048576; }
    if (i >= n4) return;
    float4 v = ((const float4*)s)[i];
    uint2 o;
    o.x = cvt2h(v.x * scale, v.y * scale);
    o.y = cvt2h(v.z * scale, v.w * scale);
    ((uint2*)d)[i] = o;
}

// ---------------- warp-MMA GEMM body (runtime flags in epilogue only) ----------------
extern __shared__ __align__(16) char smem_dyn[];

__device__ __forceinline__
void gemm_body(const __half* __restrict__ A, const __half* __restrict__ Bw,
               float* __restrict__ Cf, __half* __restrict__ Ch,
               int silu, int halfout) {
    const u32 sb = smem_u32(smem_dyn);
    const int tid = threadIdx.x, lane = tid & 31, wid = tid >> 5;
    const int l7 = lane & 7;
    const int m0 = blockIdx.y * 128, n0 = blockIdx.x * 128;
    const int wm = (wid >> 1) * 64, wn = (wid & 1) * 64;

    float acc[4][8][4];
#pragma unroll
    for (int i = 0; i < 4; i++)
#pragma unroll
        for (int j = 0; j < 8; j++)
#pragma unroll
            for (int c = 0; c < 4; c++) acc[i][j][c] = 0.0f;

    auto issue = [&](int it) {
        const int k0 = it * 64;
        const u32 base = sb + (it % 3) * 32768;
#pragma unroll
        for (int i = 0; i < 16; i++) {
            int f = tid + i * 128;             // 0..2047
            int t = f >> 10, rem = f & 1023;
            int row = rem >> 3, kc = rem & 7;
            const __half* gp = t ? Bw : A;
            int rb = t ? n0 : m0;
            const void* src = gp + (size_t)(rb + row) * 2048 + k0 + kc * 8;
            cpasync16(base + t * 16384 + SWZ((u32)(row * 128 + kc * 16)), src);
        }
    };

    issue(0); CP_COMMIT;
    issue(1); CP_COMMIT;
    for (int it = 0; it < 32; it++) {
        if (it < 31) { CP_WAIT(1); } else { CP_WAIT(0); }
        __syncthreads();
        if (it + 2 < 32) { issue(it + 2); CP_COMMIT; }
        const u32 base = sb + (it % 3) * 32768;
#pragma unroll
        for (int kk = 0; kk < 4; kk++) {
            u32 bh[16];
#pragma unroll
            for (int g = 0; g < 4; g++) {
                int nrow = wn + g * 16 + l7 + ((lane >> 4) & 1) * 8;
                int kb = kk * 32 + ((lane >> 3) & 1) * 16;
                u32 a = base + 16384 + SWZ((u32)(nrow * 128 + kb));
                ldsm4(a, bh[4 * g], bh[4 * g + 1], bh[4 * g + 2], bh[4 * g + 3]);
            }
#pragma unroll
            for (int mf = 0; mf < 4; mf++) {
                int arow = wm + mf * 16 + l7 + ((lane >> 3) & 1) * 8;
                int akb = kk * 32 + ((lane >> 4) & 1) * 16;
                u32 a0, a1, a2, a3;
                ldsm4(base + SWZ((u32)(arow * 128 + akb)), a0, a1, a2, a3);
#pragma unroll
                for (int nf = 0; nf < 8; nf++)
                    mma16816(acc[mf][nf], a0, a1, a2, a3, bh[2 * nf], bh[2 * nf + 1]);
            }
        }
    }

#pragma unroll
    for (int mf = 0; mf < 4; mf++)
#pragma unroll
        for (int nf = 0; nf < 8; nf++) {
            int row = m0 + wm + mf * 16 + (lane >> 2);
            int col = n0 + wn + nf * 8 + 2 * (lane & 3);
#pragma unroll
            for (int half = 0; half < 2; half++) {
                int r = row + half * 8;
                float v0 = acc[mf][nf][2 * half + 0];
                float v1 = acc[mf][nf][2 * half + 1];
                if (silu) { v0 = silu_f(v0); v1 = silu_f(v1); }
                size_t o = (size_t)r * 2048 + col;
                if (halfout) {
                    *(u32*)(Ch + o) = cvt2h(v0, v1);
                } else {
                    float2 w; w.x = v0; w.y = v1;
                    *(float2*)(Cf + o) = w;
                }
            }
        }
}

// merged q + gate GEMM: grid.z selects
__global__ __launch_bounds__(128, 2)
void qg_gemm(const __half* __restrict__ A,
             const __half* __restrict__ Wq, __half* __restrict__ Qout,
             const __half* __restrict__ Wg, float* __restrict__ Gout) {
    if (blockIdx.z == 0) gemm_body(A, Wq, nullptr, Qout, 0, 1);
    else                 gemm_body(A, Wg, Gout, nullptr, 1, 0);
}

__global__ __launch_bounds__(128, 2)
void out_gemm(const __half* __restrict__ A, const __half* __restrict__ Bw,
              float* __restrict__ Cf) {
    gemm_body(A, Bw, Cf, nullptr, 0, 0);
}

// ---------------- fused attention: f16-accum S (2 chains), f32 PV ----------------
// CTA = (128 q-rows, head, batch), 256 threads, 2 CTA/SM.
// Q in registers; 3-stage KV pipeline; 1 sync/iter; tanh-silu.
__global__ __launch_bounds__(256, 2)
void attn_mma(const __half* __restrict__ Q, const __half* __restrict__ Kw,
              const __half* __restrict__ Vt, const float* __restrict__ Gate,
              __half* __restrict__ O) {
    const u32 sb = smem_u32(smem_dyn);
    const int tid = threadIdx.x, lane = tid & 31, wid = tid >> 5;
    const int l7 = lane & 7;
    const int n0 = blockIdx.x * 128;
    const int h  = blockIdx.y;
    const int b  = blockIdx.z;
    const int m0w = wid * 16;
    const size_t qrow0 = (size_t)(b * 2048 + n0);

    // ---- stage Q (128x128 fp16, 32KB) into [0,32K), lift to registers
#pragma unroll
    for (int i = 0; i < 8; i++) {
        int f = tid + i * 256;             // 0..2047
        int row = f >> 4, dc = f & 15;
        const __half* src = Q + (qrow0 + row) * 2048 + h * 128 + dc * 8;
        u32 dst = sb + (u32)((dc >> 3) * 16384) + SWZ((u32)(row * 128 + (dc & 7) * 16));
        cpasync16(dst, src);
    }
    CP_COMMIT; CP_WAIT(0);
    __syncthreads();

    u32 qf[8][4];
#pragma unroll
    for (int kk = 0; kk < 8; kk++) {
        int arow = m0w + l7 + ((lane >> 3) & 1) * 8;
        int ad0 = kk * 16 + ((lane >> 4) & 1) * 8;
        u32 qa = sb + (u32)((ad0 >> 6) * 16384) + SWZ((u32)(arow * 128 + (ad0 & 63) * 2));
        ldsm4(qa, qf[kk][0], qf[kk][1], qf[kk][2], qf[kk][3]);
    }
    __syncthreads();   // everyone done reading Q before KV overwrites

    float oacc[16][4];
#pragma unroll
    for (int i = 0; i < 16; i++)
#pragma unroll
        for (int c = 0; c < 4; c++) oacc[i][c] = 0.0f;

    auto issue_kv = [&](int t) {
        const int m0k = t * 64;
        const u32 base = sb + (t % 3) * 32768;
#pragma unroll
        for (int i = 0; i < 8; i++) {
            int f = tid + i * 256;         // 0..2047
            if (f < 1024) {                // K tile: 64 keys x 128 d (two 8K d-halves)
                int key = f >> 4, dc = f & 15;
                const void* src = Kw + (size_t)(m0k + key) * 2048 + h * 128 + dc * 8;
                u32 dst = base + (dc >> 3) * 8192 + SWZ((u32)(key * 128 + (dc & 7) * 16));
                cpasync16(dst, src);
            } else {                       // V tile: 128 dv x 64 keys
                int f2 = f - 1024;
                int dv = f2 >> 3, kc = f2 & 7;
                const void* src = Vt + (size_t)(h * 128 + dv) * 4096 + m0k + kc * 8;
                cpasync16(base + 16384 + SWZ((u32)(dv * 128 + kc * 16)), src);
            }
        }
    };

    issue_kv(0); CP_COMMIT;
    issue_kv(1); CP_COMMIT;
#pragma unroll 1
    for (int t = 0; t < 64; t++) {
        if (t < 63) { CP_WAIT(1); } else { CP_WAIT(0); }
        __syncthreads();
        if (t + 2 < 64) { issue_kv(t + 2); CP_COMMIT; }
        const u32 kbase = sb + (t % 3) * 32768;

#pragma unroll
        for (int half = 0; half < 2; half++) {     // keys [32*half, 32*half+32)
            // f16 accumulators: [j][chain][reg]; chain 0 = kk 0..3, chain 1 = kk 4..7
            u32 sacc[4][2][2];
#pragma unroll
            for (int j = 0; j < 4; j++)
#pragma unroll
                for (int c = 0; c < 2; c++) { sacc[j][c][0] = 0u; sacc[j][c][1] = 0u; }

#pragma unroll
            for (int kk = 0; kk < 8; kk++) {       // d chunks of 16
                const int ch = kk >> 2;
                u32 bh[8];
#pragma unroll
                for (int g = 0; g < 2; g++) {
                    int nrow = half * 32 + g * 16 + l7 + ((lane >> 4) & 1) * 8;
                    int d0 = kk * 16 + ((lane >> 3) & 1) * 8;
                    u32 a = kbase + (d0 >> 6) * 8192 + SWZ((u32)(nrow * 128 + (d0 & 63) * 2));
                    ldsm4(a, bh[4 * g], bh[4 * g + 1], bh[4 * g + 2], bh[4 * g + 3]);
                }
#pragma unroll
                for (int j = 0; j < 4; j++)
                    mma16816h(sacc[j][ch], qf[kk][0], qf[kk][1], qf[kk][2], qf[kk][3],
                              bh[2 * j], bh[2 * j + 1]);
            }

            // merge chains in fp32, tanh-silu, pack to PV A-frags
            u32 pa[2][4];
#pragma unroll
            for (int kk2l = 0; kk2l < 2; kk2l++)
#pragma unroll
                for (int q = 0; q < 4; q++) {
                    int j = 2 * kk2l + (q >> 1);
                    int reg = q & 1;
                    __half2 ha = *reinterpret_cast<__half2*>(&sacc[j][0][reg]);
                    __half2 hb = *reinterpret_cast<__half2*>(&sacc[j][1][reg]);
                    float2 fa = __half22float2(ha);
                    float2 fb = __half22float2(hb);
                    float s0 = silu_f(fa.x + fb.x);
                    float s1 = silu_f(fa.y + fb.y);
                    pa[kk2l][q] = cvt2h(s0, s1);
                }

#pragma unroll
            for (int kk2l = 0; kk2l < 2; kk2l++) {
                int kk2 = half * 2 + kk2l;
#pragma unroll
                for (int g = 0; g < 8; g++) {
                    int nrow = g * 16 + l7 + ((lane >> 4) & 1) * 8;
                    int kb = kk2 * 32 + ((lane >> 3) & 1) * 16;
                    u32 va = kbase + 16384 + SWZ((u32)(nrow * 128 + kb));
                    u32 v0, v1, v2, v3;
                    ldsm4(va, v0, v1, v2, v3);
                    mma16816(oacc[2 * g],     pa[kk2l][0], pa[kk2l][1], pa[kk2l][2], pa[kk2l][3], v0, v1);
                    mma16816(oacc[2 * g + 1], pa[kk2l][0], pa[kk2l][1], pa[kk2l][2], pa[kk2l][3], v2, v3);
                }
            }
        }
    }

    // epilogue: gate (fp32) + fp16 store
#pragma unroll
    for (int nf = 0; nf < 16; nf++) {
        int col = nf * 8 + 2 * (lane & 3);
        int gcol = h * 128 + col;
#pragma unroll
        for (int half = 0; half < 2; half++) {
            int row = m0w + (lane >> 2) + half * 8;
            size_t o = (qrow0 + row) * 2048 + gcol;
            float2 g = *(const float2*)(Gate + o);
            float v0 = oacc[nf][2 * half + 0] * g.x;
            float v1 = oacc[nf][2 * half + 1] * g.y;
            *(u32*)(O + o) = cvt2h(v0, v1);
        }
    }
}

// ---------------- launch ----------------
#define GETSYMH(var, sym) do { void* _p; cudaGetSymbolAddress(&_p, sym); var = (__half*)_p; } while (0)

extern "C" void kernel_launch(void* const* d_in, const int* in_sizes, int n_in,
                              void* d_out, int out_size) {
    const float* x  = (const float*)d_in[0];
    const float* Wq = (const float*)d_in[1];
    const float* kw = (const float*)d_in[2];
    const float* vw = (const float*)d_in[3];
    const float* Wg = (const float*)d_in[4];
    const float* Wo = (const float*)d_in[5];
    float* out = (float*)d_out;

    __half *xh, *wq, *wg, *wo, *k, *vt, *qp, *ap;
    float* gate;
    GETSYMH(xh, g_x);
    GETSYMH(wq, g_wq); GETSYMH(wg, g_wg); GETSYMH(wo, g_wo);
    GETSYMH(k,  g_k);  GETSYMH(vt, g_vt);
    GETSYMH(qp, g_q);  GETSYMH(ap, g_a);
    { void* _p; cudaGetSymbolAddress(&_p, g_gate); gate = (float*)_p; }

    cudaFuncSetAttribute(qg_gemm,  cudaFuncAttributeMaxDynamicSharedMemorySize, 98304);
    cudaFuncSetAttribute(out_gemm, cudaFuncAttributeMaxDynamicSharedMemorySize, 98304);
    cudaFuncSetAttribute(attn_mma, cudaFuncAttributeMaxDynamicSharedMemorySize, 98304);

    // [0] merged pre-pass
    prep_kernel<<<dim3(8192, 6), 256>>>(x, xh, kw, k, Wq, wq, Wg, wg, Wo, wo, vw, vt);
    // [1] merged q + gate GEMM
    qg_gemm<<<dim3(16, 32, 2), 128, 98304>>>(xh, wq, qp, wg, gate);
    // [2] attention
    attn_mma<<<dim3(16, 16, 2), 256, 98304>>>(qp, k, vt, gate, ap);
    // [3] output GEMM
    out_gemm<<<dim3(16, 32), 128, 98304>>>(ap, wo, out);
}

// round 14
// speedup vs baseline: 1.0004x; 1.0004x over previous
#include <cuda_runtime.h>
#include <cuda_fp16.h>

typedef unsigned int u32;

#define SCALE_F 11.313708498984761f   // sqrt(128)

// ---------------- scratch (all single fp16; gate fp32) ----------------
static __device__ __half g_x[8388608];
static __device__ __half g_wq[4194304], g_wg[4194304], g_wo[4194304];
static __device__ __half g_k[8388608];
static __device__ __half g_vt[8388608];
static __device__ __half g_q[8388608];
static __device__ float  g_gate[8388608];
static __device__ __half g_a[8388608];

// ---------------- helpers ----------------
__device__ __forceinline__ u32 smem_u32(const void* p) {
    u32 a;
    asm("{ .reg .u64 t; cvta.to.shared.u64 t, %1; cvt.u32.u64 %0, t; }" : "=r"(a) : "l"(p));
    return a;
}
#define SWZ(o) ((o) ^ (((o) >> 3) & 0x70))

__device__ __forceinline__ void ldsm4(u32 addr, u32& r0, u32& r1, u32& r2, u32& r3) {
    asm volatile("ldmatrix.sync.aligned.m8n8.x4.shared.b16 {%0,%1,%2,%3}, [%4];"
                 : "=r"(r0), "=r"(r1), "=r"(r2), "=r"(r3) : "r"(addr));
}
__device__ __forceinline__ void mma16816(float (&d)[4], u32 a0, u32 a1, u32 a2, u32 a3,
                                         u32 b0, u32 b1) {
    asm volatile(
        "mma.sync.aligned.m16n8k16.row.col.f32.f16.f16.f32 "
        "{%0,%1,%2,%3},{%4,%5,%6,%7},{%8,%9},{%0,%1,%2,%3};"
        : "+f"(d[0]), "+f"(d[1]), "+f"(d[2]), "+f"(d[3])
        : "r"(a0), "r"(a1), "r"(a2), "r"(a3), "r"(b0), "r"(b1));
}
// fp16-accumulator variant (C/D = 2 x b32 packed halves)
__device__ __forceinline__ void mma16816h(u32 (&d)[2], u32 a0, u32 a1, u32 a2, u32 a3,
                                          u32 b0, u32 b1) {
    asm volatile(
        "mma.sync.aligned.m16n8k16.row.col.f16.f16.f16.f16 "
        "{%0,%1},{%2,%3,%4,%5},{%6,%7},{%0,%1};"
        : "+r"(d[0]), "+r"(d[1])
        : "r"(a0), "r"(a1), "r"(a2), "r"(a3), "r"(b0), "r"(b1));
}
__device__ __forceinline__ void cpasync16(u32 dst, const void* src) {
    asm volatile("cp.async.cg.shared.global [%0], [%1], 16;" :: "r"(dst), "l"(src));
}
#define CP_COMMIT asm volatile("cp.async.commit_group;" ::: "memory")
#define CP_WAIT(n) asm volatile("cp.async.wait_group %0;" :: "n"(n) : "memory")

// silu via tanh.approx: 1 MUFU + 2 fma
__device__ __forceinline__ float silu_f(float x) {
    float h = 0.5f * x;
    float t;
    asm("tanh.approx.f32 %0, %1;" : "=f"(t) : "f"(h));
    return fmaf(h, t, h);
}
// pack two f32 -> f16x2 in one cvt (lo = first arg)
__device__ __forceinline__ u32 cvt2h(float lo, float hi) {
    u32 d;
    asm("cvt.rn.f16x2.f32 %0, %1, %2;" : "=r"(d) : "f"(hi), "f"(lo));
    return d;
}

// ---------------- merged pre-pass: one launch ----------------
__global__ void prep_kernel(const float* __restrict__ x,  __half* __restrict__ dx,
                            const float* __restrict__ kw, __half* __restrict__ dk,
                            const float* __restrict__ wq, __half* __restrict__ dq,
                            const float* __restrict__ wg, __half* __restrict__ dg,
                            const float* __restrict__ wo, __half* __restrict__ dw,
                            const float* __restrict__ vw, __half* __restrict__ dvt) {
    const int y = blockIdx.y;
    if (y == 5) {
        __shared__ float sm[32][33];
        int c0 = (blockIdx.x & 63) * 32;
        int m0 = (blockIdx.x >> 6) * 32;
        int tx = threadIdx.x & 31, ty = threadIdx.x >> 5;
#pragma unroll
        for (int j = 0; j < 4; j++)
            sm[ty + 8 * j][tx] = vw[(size_t)(m0 + ty + 8 * j) * 2048 + c0 + tx] * SCALE_F;
        __syncthreads();
#pragma unroll
        for (int j = 0; j < 4; j++)
            dvt[(size_t)(c0 + ty + 8 * j) * 4096 + m0 + tx] = __float2half_rn(sm[tx][ty + 8 * j]);
        return;
    }
    int i = blockIdx.x * blockDim.x + threadIdx.x;
    const float* s;
    __half* d;
    float scale = 1.0f;
    int n4;
    if (y == 0)      { s = x;  d = dx; n4 = 2097152; }
    else if (y == 1) { s = kw; d = dk; n4 = 2097152; scale = SCALE_F; }
    else if (y == 2) { s = wq; d = dq; n4 = 1048576; }
    else if (y == 3) { s = wg; d = dg; n4 = 1048576; }
    else             { s = wo; d = dw; n4 = 1048576; }
    if (i >= n4) return;
    float4 v = ((const float4*)s)[i];
    uint2 o;
    o.x = cvt2h(v.x * scale, v.y * scale);
    o.y = cvt2h(v.z * scale, v.w * scale);
    ((uint2*)d)[i] = o;
}

// ---------------- warp-MMA GEMM body (runtime flags in epilogue only) ----------------
extern __shared__ __align__(16) char smem_dyn[];

__device__ __forceinline__
void gemm_body(const __half* __restrict__ A, const __half* __restrict__ Bw,
               float* __restrict__ Cf, __half* __restrict__ Ch,
               int silu, int halfout) {
    const u32 sb = smem_u32(smem_dyn);
    const int tid = threadIdx.x, lane = tid & 31, wid = tid >> 5;
    const int l7 = lane & 7;
    const int m0 = blockIdx.y * 128, n0 = blockIdx.x * 128;
    const int wm = (wid >> 1) * 64, wn = (wid & 1) * 64;

    float acc[4][8][4];
#pragma unroll
    for (int i = 0; i < 4; i++)
#pragma unroll
        for (int j = 0; j < 8; j++)
#pragma unroll
            for (int c = 0; c < 4; c++) acc[i][j][c] = 0.0f;

    auto issue = [&](int it) {
        const int k0 = it * 64;
        const u32 base = sb + (it % 3) * 32768;
#pragma unroll
        for (int i = 0; i < 16; i++) {
            int f = tid + i * 128;             // 0..2047
            int t = f >> 10, rem = f & 1023;
            int row = rem >> 3, kc = rem & 7;
            const __half* gp = t ? Bw : A;
            int rb = t ? n0 : m0;
            const void* src = gp + (size_t)(rb + row) * 2048 + k0 + kc * 8;
            cpasync16(base + t * 16384 + SWZ((u32)(row * 128 + kc * 16)), src);
        }
    };

    issue(0); CP_COMMIT;
    issue(1); CP_COMMIT;
    for (int it = 0; it < 32; it++) {
        if (it < 31) { CP_WAIT(1); } else { CP_WAIT(0); }
        __syncthreads();
        if (it + 2 < 32) { issue(it + 2); CP_COMMIT; }
        const u32 base = sb + (it % 3) * 32768;
#pragma unroll
        for (int kk = 0; kk < 4; kk++) {
            u32 bh[16];
#pragma unroll
            for (int g = 0; g < 4; g++) {
                int nrow = wn + g * 16 + l7 + ((lane >> 4) & 1) * 8;
                int kb = kk * 32 + ((lane >> 3) & 1) * 16;
                u32 a = base + 16384 + SWZ((u32)(nrow * 128 + kb));
                ldsm4(a, bh[4 * g], bh[4 * g + 1], bh[4 * g + 2], bh[4 * g + 3]);
            }
#pragma unroll
            for (int mf = 0; mf < 4; mf++) {
                int arow = wm + mf * 16 + l7 + ((lane >> 3) & 1) * 8;
                int akb = kk * 32 + ((lane >> 4) & 1) * 16;
                u32 a0, a1, a2, a3;
                ldsm4(base + SWZ((u32)(arow * 128 + akb)), a0, a1, a2, a3);
#pragma unroll
                for (int nf = 0; nf < 8; nf++)
                    mma16816(acc[mf][nf], a0, a1, a2, a3, bh[2 * nf], bh[2 * nf + 1]);
            }
        }
    }

#pragma unroll
    for (int mf = 0; mf < 4; mf++)
#pragma unroll
        for (int nf = 0; nf < 8; nf++) {
            int row = m0 + wm + mf * 16 + (lane >> 2);
            int col = n0 + wn + nf * 8 + 2 * (lane & 3);
#pragma unroll
            for (int half = 0; half < 2; half++) {
                int r = row + half * 8;
                float v0 = acc[mf][nf][2 * half + 0];
                float v1 = acc[mf][nf][2 * half + 1];
                if (silu) { v0 = silu_f(v0); v1 = silu_f(v1); }
                size_t o = (size_t)r * 2048 + col;
                if (halfout) {
                    *(u32*)(Ch + o) = cvt2h(v0, v1);
                } else {
                    float2 w; w.x = v0; w.y = v1;
                    *(float2*)(Cf + o) = w;
                }
            }
        }
}

// merged q + gate GEMM: grid.z selects
__global__ __launch_bounds__(128, 2)
void qg_gemm(const __half* __restrict__ A,
             const __half* __restrict__ Wq, __half* __restrict__ Qout,
             const __half* __restrict__ Wg, float* __restrict__ Gout) {
    if (blockIdx.z == 0) gemm_body(A, Wq, nullptr, Qout, 0, 1);
    else                 gemm_body(A, Wg, Gout, nullptr, 1, 0);
}

__global__ __launch_bounds__(128, 2)
void out_gemm(const __half* __restrict__ A, const __half* __restrict__ Bw,
              float* __restrict__ Cf) {
    gemm_body(A, Bw, Cf, nullptr, 0, 0);
}

// ---------------- fused attention: f16-accum S (2 chains), f32 PV ----------------
// CTA = (128 q-rows, head, batch), 256 threads, 2 CTA/SM.
// Q in registers; 3-stage KV pipeline; 1 sync/iter; tanh-silu.
__global__ __launch_bounds__(256, 2)
void attn_mma(const __half* __restrict__ Q, const __half* __restrict__ Kw,
              const __half* __restrict__ Vt, const float* __restrict__ Gate,
              __half* __restrict__ O) {
    const u32 sb = smem_u32(smem_dyn);
    const int tid = threadIdx.x, lane = tid & 31, wid = tid >> 5;
    const int l7 = lane & 7;
    const int n0 = blockIdx.x * 128;
    const int h  = blockIdx.y;
    const int b  = blockIdx.z;
    const int m0w = wid * 16;
    const size_t qrow0 = (size_t)(b * 2048 + n0);

    // ---- stage Q (128x128 fp16, 32KB) into [0,32K), lift to registers
#pragma unroll
    for (int i = 0; i < 8; i++) {
        int f = tid + i * 256;             // 0..2047
        int row = f >> 4, dc = f & 15;
        const __half* src = Q + (qrow0 + row) * 2048 + h * 128 + dc * 8;
        u32 dst = sb + (u32)((dc >> 3) * 16384) + SWZ((u32)(row * 128 + (dc & 7) * 16));
        cpasync16(dst, src);
    }
    CP_COMMIT; CP_WAIT(0);
    __syncthreads();

    u32 qf[8][4];
#pragma unroll
    for (int kk = 0; kk < 8; kk++) {
        int arow = m0w + l7 + ((lane >> 3) & 1) * 8;
        int ad0 = kk * 16 + ((lane >> 4) & 1) * 8;
        u32 qa = sb + (u32)((ad0 >> 6) * 16384) + SWZ((u32)(arow * 128 + (ad0 & 63) * 2));
        ldsm4(qa, qf[kk][0], qf[kk][1], qf[kk][2], qf[kk][3]);
    }
    __syncthreads();   // everyone done reading Q before KV overwrites

    float oacc[16][4];
#pragma unroll
    for (int i = 0; i < 16; i++)
#pragma unroll
        for (int c = 0; c < 4; c++) oacc[i][c] = 0.0f;

    auto issue_kv = [&](int t) {
        const int m0k = t * 64;
        const u32 base = sb + (t % 3) * 32768;
#pragma unroll
        for (int i = 0; i < 8; i++) {
            int f = tid + i * 256;         // 0..2047
            if (f < 1024) {                // K tile: 64 keys x 128 d (two 8K d-halves)
                int key = f >> 4, dc = f & 15;
                const void* src = Kw + (size_t)(m0k + key) * 2048 + h * 128 + dc * 8;
                u32 dst = base + (dc >> 3) * 8192 + SWZ((u32)(key * 128 + (dc & 7) * 16));
                cpasync16(dst, src);
            } else {                       // V tile: 128 dv x 64 keys
                int f2 = f - 1024;
                int dv = f2 >> 3, kc = f2 & 7;
                const void* src = Vt + (size_t)(h * 128 + dv) * 4096 + m0k + kc * 8;
                cpasync16(base + 16384 + SWZ((u32)(dv * 128 + kc * 16)), src);
            }
        }
    };

    issue_kv(0); CP_COMMIT;
    issue_kv(1); CP_COMMIT;
#pragma unroll 1
    for (int t = 0; t < 64; t++) {
        if (t < 63) { CP_WAIT(1); } else { CP_WAIT(0); }
        __syncthreads();
        if (t + 2 < 64) { issue_kv(t + 2); CP_COMMIT; }
        const u32 kbase = sb + (t % 3) * 32768;

#pragma unroll
        for (int half = 0; half < 2; half++) {     // keys [32*half, 32*half+32)
            // f16 accumulators: [j][chain][reg]; chain 0 = kk 0..3, chain 1 = kk 4..7
            u32 sacc[4][2][2];
#pragma unroll
            for (int j = 0; j < 4; j++)
#pragma unroll
                for (int c = 0; c < 2; c++) { sacc[j][c][0] = 0u; sacc[j][c][1] = 0u; }

#pragma unroll
            for (int kk = 0; kk < 8; kk++) {       // d chunks of 16
                const int ch = kk >> 2;
                u32 bh[8];
#pragma unroll
                for (int g = 0; g < 2; g++) {
                    int nrow = half * 32 + g * 16 + l7 + ((lane >> 4) & 1) * 8;
                    int d0 = kk * 16 + ((lane >> 3) & 1) * 8;
                    u32 a = kbase + (d0 >> 6) * 8192 + SWZ((u32)(nrow * 128 + (d0 & 63) * 2));
                    ldsm4(a, bh[4 * g], bh[4 * g + 1], bh[4 * g + 2], bh[4 * g + 3]);
                }
#pragma unroll
                for (int j = 0; j < 4; j++)
                    mma16816h(sacc[j][ch], qf[kk][0], qf[kk][1], qf[kk][2], qf[kk][3],
                              bh[2 * j], bh[2 * j + 1]);
            }

            // merge chains in fp32, tanh-silu, pack to PV A-frags
            u32 pa[2][4];
#pragma unroll
            for (int kk2l = 0; kk2l < 2; kk2l++)
#pragma unroll
                for (int q = 0; q < 4; q++) {
                    int j = 2 * kk2l + (q >> 1);
                    int reg = q & 1;
                    __half2 ha = *reinterpret_cast<__half2*>(&sacc[j][0][reg]);
                    __half2 hb = *reinterpret_cast<__half2*>(&sacc[j][1][reg]);
                    float2 fa = __half22float2(ha);
                    float2 fb = __half22float2(hb);
                    float s0 = silu_f(fa.x + fb.x);
                    float s1 = silu_f(fa.y + fb.y);
                    pa[kk2l][q] = cvt2h(s0, s1);
                }

#pragma unroll
            for (int kk2l = 0; kk2l < 2; kk2l++) {
                int kk2 = half * 2 + kk2l;
#pragma unroll
                for (int g = 0; g < 8; g++) {
                    int nrow = g * 16 + l7 + ((lane >> 4) & 1) * 8;
                    int kb = kk2 * 32 + ((lane >> 3) & 1) * 16;
                    u32 va = kbase + 16384 + SWZ((u32)(nrow * 128 + kb));
                    u32 v0, v1, v2, v3;
                    ldsm4(va, v0, v1, v2, v3);
                    mma16816(oacc[2 * g],     pa[kk2l][0], pa[kk2l][1], pa[kk2l][2], pa[kk2l][3], v0, v1);
                    mma16816(oacc[2 * g + 1], pa[kk2l][0], pa[kk2l][1], pa[kk2l][2], pa[kk2l][3], v2, v3);
                }
            }
        }
    }

    // epilogue: gate (fp32) + fp16 store
#pragma unroll
    for (int nf = 0; nf < 16; nf++) {
        int col = nf * 8 + 2 * (lane & 3);
        int gcol = h * 128 + col;
#pragma unroll
        for (int half = 0; half < 2; half++) {
            int row = m0w + (lane >> 2) + half * 8;
            size_t o = (qrow0 + row) * 2048 + gcol;
            float2 g = *(const float2*)(Gate + o);
            float v0 = oacc[nf][2 * half + 0] * g.x;
            float v1 = oacc[nf][2 * half + 1] * g.y;
            *(u32*)(O + o) = cvt2h(v0, v1);
        }
    }
}

// ---------------- launch ----------------
#define GETSYMH(var, sym) do { void* _p; cudaGetSymbolAddress(&_p, sym); var = (__half*)_p; } while (0)

extern "C" void kernel_launch(void* const* d_in, const int* in_sizes, int n_in,
                              void* d_out, int out_size) {
    const float* x  = (const float*)d_in[0];
    const float* Wq = (const float*)d_in[1];
    const float* kw = (const float*)d_in[2];
    const float* vw = (const float*)d_in[3];
    const float* Wg = (const float*)d_in[4];
    const float* Wo = (const float*)d_in[5];
    float* out = (float*)d_out;

    __half *xh, *wq, *wg, *wo, *k, *vt, *qp, *ap;
    float* gate;
    GETSYMH(xh, g_x);
    GETSYMH(wq, g_wq); GETSYMH(wg, g_wg); GETSYMH(wo, g_wo);
    GETSYMH(k,  g_k);  GETSYMH(vt, g_vt);
    GETSYMH(qp, g_q);  GETSYMH(ap, g_a);
    { void* _p; cudaGetSymbolAddress(&_p, g_gate); gate = (float*)_p; }

    cudaFuncSetAttribute(qg_gemm,  cudaFuncAttributeMaxDynamicSharedMemorySize, 98304);
    cudaFuncSetAttribute(out_gemm, cudaFuncAttributeMaxDynamicSharedMemorySize, 98304);
    cudaFuncSetAttribute(attn_mma, cudaFuncAttributeMaxDynamicSharedMemorySize, 98304);

    // [0] merged pre-pass
    prep_kernel<<<dim3(8192, 6), 256>>>(x, xh, kw, k, Wq, wq, Wg, wg, Wo, wo, vw, vt);
    // [1] merged q + gate GEMM
    qg_gemm<<<dim3(16, 32, 2), 128, 98304>>>(xh, wq, qp, wg, gate);
    // [2] attention
    attn_mma<<<dim3(16, 16, 2), 256, 98304>>>(qp, k, vt, gate, ap);
    // [3] output GEMM
    out_gemm<<<dim3(16, 32), 128, 98304>>>(ap, wo, out);
}

// round 15
// speedup vs baseline: 1.0028x; 1.0024x over previous
#include <cuda_runtime.h>
#include <cuda_fp16.h>

typedef unsigned int u32;

#define SCALE_F 11.313708498984761f   // sqrt(128)

// ---------------- scratch (all single fp16; gate fp32) ----------------
static __device__ __half g_x[8388608];
static __device__ __half g_wq[4194304], g_wg[4194304], g_wo[4194304];
static __device__ __half g_k[8388608];
static __device__ __half g_vt[8388608];
static __device__ __half g_q[8388608];
static __device__ float  g_gate[8388608];
static __device__ __half g_a[8388608];

// ---------------- helpers ----------------
__device__ __forceinline__ u32 smem_u32(const void* p) {
    u32 a;
    asm("{ .reg .u64 t; cvta.to.shared.u64 t, %1; cvt.u32.u64 %0, t; }" : "=r"(a) : "l"(p));
    return a;
}
#define SWZ(o) ((o) ^ (((o) >> 3) & 0x70))

__device__ __forceinline__ void ldsm4(u32 addr, u32& r0, u32& r1, u32& r2, u32& r3) {
    asm volatile("ldmatrix.sync.aligned.m8n8.x4.shared.b16 {%0,%1,%2,%3}, [%4];"
                 : "=r"(r0), "=r"(r1), "=r"(r2), "=r"(r3) : "r"(addr));
}
__device__ __forceinline__ void mma16816(float (&d)[4], u32 a0, u32 a1, u32 a2, u32 a3,
                                         u32 b0, u32 b1) {
    asm volatile(
        "mma.sync.aligned.m16n8k16.row.col.f32.f16.f16.f32 "
        "{%0,%1,%2,%3},{%4,%5,%6,%7},{%8,%9},{%0,%1,%2,%3};"
        : "+f"(d[0]), "+f"(d[1]), "+f"(d[2]), "+f"(d[3])
        : "r"(a0), "r"(a1), "r"(a2), "r"(a3), "r"(b0), "r"(b1));
}
// fp16-accumulator variant (C/D = 2 x b32 packed halves)
__device__ __forceinline__ void mma16816h(u32 (&d)[2], u32 a0, u32 a1, u32 a2, u32 a3,
                                          u32 b0, u32 b1) {
    asm volatile(
        "mma.sync.aligned.m16n8k16.row.col.f16.f16.f16.f16 "
        "{%0,%1},{%2,%3,%4,%5},{%6,%7},{%0,%1};"
        : "+r"(d[0]), "+r"(d[1])
        : "r"(a0), "r"(a1), "r"(a2), "r"(a3), "r"(b0), "r"(b1));
}
__device__ __forceinline__ void cpasync16(u32 dst, const void* src) {
    asm volatile("cp.async.cg.shared.global [%0], [%1], 16;" :: "r"(dst), "l"(src));
}
#define CP_COMMIT asm volatile("cp.async.commit_group;" ::: "memory")
#define CP_WAIT(n) asm volatile("cp.async.wait_group %0;" :: "n"(n) : "memory")

// silu via tanh.approx: 1 MUFU + 2 fma
__device__ __forceinline__ float silu_f(float x) {
    float h = 0.5f * x;
    float t;
    asm("tanh.approx.f32 %0, %1;" : "=f"(t) : "f"(h));
    return fmaf(h, t, h);
}
// pack two f32 -> f16x2 in one cvt (lo = first arg)
__device__ __forceinline__ u32 cvt2h(float lo, float hi) {
    u32 d;
    asm("cvt.rn.f16x2.f32 %0, %1, %2;" : "=r"(d) : "f"(hi), "f"(lo));
    return d;
}

// ---------------- merged pre-pass: one launch ----------------
__global__ void prep_kernel(const float* __restrict__ x,  __half* __restrict__ dx,
                            const float* __restrict__ kw, __half* __restrict__ dk,
                            const float* __restrict__ wq, __half* __restrict__ dq,
                            const float* __restrict__ wg, __half* __restrict__ dg,
                            const float* __restrict__ wo, __half* __restrict__ dw,
                            const float* __restrict__ vw, __half* __restrict__ dvt) {
    const int y = blockIdx.y;
    if (y == 5) {
        __shared__ float sm[32][33];
        int c0 = (blockIdx.x & 63) * 32;
        int m0 = (blockIdx.x >> 6) * 32;
        int tx = threadIdx.x & 31, ty = threadIdx.x >> 5;
#pragma unroll
        for (int j = 0; j < 4; j++)
            sm[ty + 8 * j][tx] = vw[(size_t)(m0 + ty + 8 * j) * 2048 + c0 + tx] * SCALE_F;
        __syncthreads();
#pragma unroll
        for (int j = 0; j < 4; j++)
            dvt[(size_t)(c0 + ty + 8 * j) * 4096 + m0 + tx] = __float2half_rn(sm[tx][ty + 8 * j]);
        return;
    }
    int i = blockIdx.x * blockDim.x + threadIdx.x;
    const float* s;
    __half* d;
    float scale = 1.0f;
    int n4;
    if (y == 0)      { s = x;  d = dx; n4 = 2097152; }
    else if (y == 1) { s = kw; d = dk; n4 = 2097152; scale = SCALE_F; }
    else if (y == 2) { s = wq; d = dq; n4 = 1048576; }
    else if (y == 3) { s = wg; d = dg; n4 = 1048576; }
    else             { s = wo; d = dw; n4 = 1048576; }
    if (i >= n4) return;
    float4 v = ((const float4*)s)[i];
    uint2 o;
    o.x = cvt2h(v.x * scale, v.y * scale);
    o.y = cvt2h(v.z * scale, v.w * scale);
    ((uint2*)d)[i] = o;
}

// ---------------- warp-MMA GEMM body (runtime flags in epilogue only) ----------------
extern __shared__ __align__(16) char smem_dyn[];

__device__ __forceinline__
void gemm_body(const __half* __restrict__ A, const __half* __restrict__ Bw,
               float* __restrict__ Cf, __half* __restrict__ Ch,
               int silu, int halfout) {
    const u32 sb = smem_u32(smem_dyn);
    const int tid = threadIdx.x, lane = tid & 31, wid = tid >> 5;
    const int l7 = lane & 7;
    const int m0 = blockIdx.y * 128, n0 = blockIdx.x * 128;
    const int wm = (wid >> 1) * 64, wn = (wid & 1) * 64;

    float acc[4][8][4];
#pragma unroll
    for (int i = 0; i < 4; i++)
#pragma unroll
        for (int j = 0; j < 8; j++)
#pragma unroll
            for (int c = 0; c < 4; c++) acc[i][j][c] = 0.0f;

    auto issue = [&](int it) {
        const int k0 = it * 64;
        const u32 base = sb + (it % 3) * 32768;
#pragma unroll
        for (int i = 0; i < 16; i++) {
            int f = tid + i * 128;             // 0..2047
            int t = f >> 10, rem = f & 1023;
            int row = rem >> 3, kc = rem & 7;
            const __half* gp = t ? Bw : A;
            int rb = t ? n0 : m0;
            const void* src = gp + (size_t)(rb + row) * 2048 + k0 + kc * 8;
            cpasync16(base + t * 16384 + SWZ((u32)(row * 128 + kc * 16)), src);
        }
    };

    issue(0); CP_COMMIT;
    issue(1); CP_COMMIT;
    for (int it = 0; it < 32; it++) {
        if (it < 31) { CP_WAIT(1); } else { CP_WAIT(0); }
        __syncthreads();
        if (it + 2 < 32) { issue(it + 2); CP_COMMIT; }
        const u32 base = sb + (it % 3) * 32768;
#pragma unroll
        for (int kk = 0; kk < 4; kk++) {
            u32 bh[16];
#pragma unroll
            for (int g = 0; g < 4; g++) {
                int nrow = wn + g * 16 + l7 + ((lane >> 4) & 1) * 8;
                int kb = kk * 32 + ((lane >> 3) & 1) * 16;
                u32 a = base + 16384 + SWZ((u32)(nrow * 128 + kb));
                ldsm4(a, bh[4 * g], bh[4 * g + 1], bh[4 * g + 2], bh[4 * g + 3]);
            }
#pragma unroll
            for (int mf = 0; mf < 4; mf++) {
                int arow = wm + mf * 16 + l7 + ((lane >> 3) & 1) * 8;
                int akb = kk * 32 + ((lane >> 4) & 1) * 16;
                u32 a0, a1, a2, a3;
                ldsm4(base + SWZ((u32)(arow * 128 + akb)), a0, a1, a2, a3);
#pragma unroll
                for (int nf = 0; nf < 8; nf++)
                    mma16816(acc[mf][nf], a0, a1, a2, a3, bh[2 * nf], bh[2 * nf + 1]);
            }
        }
    }

#pragma unroll
    for (int mf = 0; mf < 4; mf++)
#pragma unroll
        for (int nf = 0; nf < 8; nf++) {
            int row = m0 + wm + mf * 16 + (lane >> 2);
            int col = n0 + wn + nf * 8 + 2 * (lane & 3);
#pragma unroll
            for (int half = 0; half < 2; half++) {
                int r = row + half * 8;
                float v0 = acc[mf][nf][2 * half + 0];
                float v1 = acc[mf][nf][2 * half + 1];
                if (silu) { v0 = silu_f(v0); v1 = silu_f(v1); }
                size_t o = (size_t)r * 2048 + col;
                if (halfout) {
                    *(u32*)(Ch + o) = cvt2h(v0, v1);
                } else {
                    float2 w; w.x = v0; w.y = v1;
                    *(float2*)(Cf + o) = w;
                }
            }
        }
}

// merged q + gate GEMM: grid.z selects
__global__ __launch_bounds__(128, 2)
void qg_gemm(const __half* __restrict__ A,
             const __half* __restrict__ Wq, __half* __restrict__ Qout,
             const __half* __restrict__ Wg, float* __restrict__ Gout) {
    if (blockIdx.z == 0) gemm_body(A, Wq, nullptr, Qout, 0, 1);
    else                 gemm_body(A, Wg, Gout, nullptr, 1, 0);
}

__global__ __launch_bounds__(128, 2)
void out_gemm(const __half* __restrict__ A, const __half* __restrict__ Bw,
              float* __restrict__ Cf) {
    gemm_body(A, Bw, Cf, nullptr, 0, 0);
}

// ---------------- fused attention: f16-accum S (2 chains), f32 PV ----------------
// CTA = (128 q-rows, head, batch), 256 threads, 2 CTA/SM.
// Q in registers; 3-stage KV pipeline; 1 sync/iter; tanh-silu.
__global__ __launch_bounds__(256, 2)
void attn_mma(const __half* __restrict__ Q, const __half* __restrict__ Kw,
              const __half* __restrict__ Vt, const float* __restrict__ Gate,
              __half* __restrict__ O) {
    const u32 sb = smem_u32(smem_dyn);
    const int tid = threadIdx.x, lane = tid & 31, wid = tid >> 5;
    const int l7 = lane & 7;
    const int n0 = blockIdx.x * 128;
    const int h  = blockIdx.y;
    const int b  = blockIdx.z;
    const int m0w = wid * 16;
    const size_t qrow0 = (size_t)(b * 2048 + n0);

    // ---- stage Q (128x128 fp16, 32KB) into [0,32K), lift to registers
#pragma unroll
    for (int i = 0; i < 8; i++) {
        int f = tid + i * 256;             // 0..2047
        int row = f >> 4, dc = f & 15;
        const __half* src = Q + (qrow0 + row) * 2048 + h * 128 + dc * 8;
        u32 dst = sb + (u32)((dc >> 3) * 16384) + SWZ((u32)(row * 128 + (dc & 7) * 16));
        cpasync16(dst, src);
    }
    CP_COMMIT; CP_WAIT(0);
    __syncthreads();

    u32 qf[8][4];
#pragma unroll
    for (int kk = 0; kk < 8; kk++) {
        int arow = m0w + l7 + ((lane >> 3) & 1) * 8;
        int ad0 = kk * 16 + ((lane >> 4) & 1) * 8;
        u32 qa = sb + (u32)((ad0 >> 6) * 16384) + SWZ((u32)(arow * 128 + (ad0 & 63) * 2));
        ldsm4(qa, qf[kk][0], qf[kk][1], qf[kk][2], qf[kk][3]);
    }
    __syncthreads();   // everyone done reading Q before KV overwrites

    float oacc[16][4];
#pragma unroll
    for (int i = 0; i < 16; i++)
#pragma unroll
        for (int c = 0; c < 4; c++) oacc[i][c] = 0.0f;

    auto issue_kv = [&](int t) {
        const int m0k = t * 64;
        const u32 base = sb + (t % 3) * 32768;
#pragma unroll
        for (int i = 0; i < 8; i++) {
            int f = tid + i * 256;         // 0..2047
            if (f < 1024) {                // K tile: 64 keys x 128 d (two 8K d-halves)
                int key = f >> 4, dc = f & 15;
                const void* src = Kw + (size_t)(m0k + key) * 2048 + h * 128 + dc * 8;
                u32 dst = base + (dc >> 3) * 8192 + SWZ((u32)(key * 128 + (dc & 7) * 16));
                cpasync16(dst, src);
            } else {                       // V tile: 128 dv x 64 keys
                int f2 = f - 1024;
                int dv = f2 >> 3, kc = f2 & 7;
                const void* src = Vt + (size_t)(h * 128 + dv) * 4096 + m0k + kc * 8;
                cpasync16(base + 16384 + SWZ((u32)(dv * 128 + kc * 16)), src);
            }
        }
    };

    issue_kv(0); CP_COMMIT;
    issue_kv(1); CP_COMMIT;
#pragma unroll 1
    for (int t = 0; t < 64; t++) {
        if (t < 63) { CP_WAIT(1); } else { CP_WAIT(0); }
        __syncthreads();
        if (t + 2 < 64) { issue_kv(t + 2); CP_COMMIT; }
        const u32 kbase = sb + (t % 3) * 32768;

#pragma unroll
        for (int half = 0; half < 2; half++) {     // keys [32*half, 32*half+32)
            // f16 accumulators: [j][chain][reg]; chain 0 = kk 0..3, chain 1 = kk 4..7
            u32 sacc[4][2][2];
#pragma unroll
            for (int j = 0; j < 4; j++)
#pragma unroll
                for (int c = 0; c < 2; c++) { sacc[j][c][0] = 0u; sacc[j][c][1] = 0u; }

#pragma unroll
            for (int kk = 0; kk < 8; kk++) {       // d chunks of 16
                const int ch = kk >> 2;
                u32 bh[8];
#pragma unroll
                for (int g = 0; g < 2; g++) {
                    int nrow = half * 32 + g * 16 + l7 + ((lane >> 4) & 1) * 8;
                    int d0 = kk * 16 + ((lane >> 3) & 1) * 8;
                    u32 a = kbase + (d0 >> 6) * 8192 + SWZ((u32)(nrow * 128 + (d0 & 63) * 2));
                    ldsm4(a, bh[4 * g], bh[4 * g + 1], bh[4 * g + 2], bh[4 * g + 3]);
                }
#pragma unroll
                for (int j = 0; j < 4; j++)
                    mma16816h(sacc[j][ch], qf[kk][0], qf[kk][1], qf[kk][2], qf[kk][3],
                              bh[2 * j], bh[2 * j + 1]);
            }

            // merge chains in fp32, tanh-silu, pack to PV A-frags
            u32 pa[2][4];
#pragma unroll
            for (int kk2l = 0; kk2l < 2; kk2l++)
#pragma unroll
                for (int q = 0; q < 4; q++) {
                    int j = 2 * kk2l + (q >> 1);
                    int reg = q & 1;
                    __half2 ha = *reinterpret_cast<__half2*>(&sacc[j][0][reg]);
                    __half2 hb = *reinterpret_cast<__half2*>(&sacc[j][1][reg]);
                    float2 fa = __half22float2(ha);
                    float2 fb = __half22float2(hb);
                    float s0 = silu_f(fa.x + fb.x);
                    float s1 = silu_f(fa.y + fb.y);
                    pa[kk2l][q] = cvt2h(s0, s1);
                }

#pragma unroll
            for (int kk2l = 0; kk2l < 2; kk2l++) {
                int kk2 = half * 2 + kk2l;
#pragma unroll
                for (int g = 0; g < 8; g++) {
                    int nrow = g * 16 + l7 + ((lane >> 4) & 1) * 8;
                    int kb = kk2 * 32 + ((lane >> 3) & 1) * 16;
                    u32 va = kbase + 16384 + SWZ((u32)(nrow * 128 + kb));
                    u32 v0, v1, v2, v3;
                    ldsm4(va, v0, v1, v2, v3);
                    mma16816(oacc[2 * g],     pa[kk2l][0], pa[kk2l][1], pa[kk2l][2], pa[kk2l][3], v0, v1);
                    mma16816(oacc[2 * g + 1], pa[kk2l][0], pa[kk2l][1], pa[kk2l][2], pa[kk2l][3], v2, v3);
                }
            }
        }
    }

    // epilogue: gate (fp32) + fp16 store
#pragma unroll
    for (int nf = 0; nf < 16; nf++) {
        int col = nf * 8 + 2 * (lane & 3);
        int gcol = h * 128 + col;
#pragma unroll
        for (int half = 0; half < 2; half++) {
            int row = m0w + (lane >> 2) + half * 8;
            size_t o = (qrow0 + row) * 2048 + gcol;
            float2 g = *(const float2*)(Gate + o);
            float v0 = oacc[nf][2 * half + 0] * g.x;
            float v1 = oacc[nf][2 * half + 1] * g.y;
            *(u32*)(O + o) = cvt2h(v0, v1);
        }
    }
}

// ---------------- launch ----------------
#define GETSYMH(var, sym) do { void* _p; cudaGetSymbolAddress(&_p, sym); var = (__half*)_p; } while (0)

extern "C" void kernel_launch(void* const* d_in, const int* in_sizes, int n_in,
                              void* d_out, int out_size) {
    const float* x  = (const float*)d_in[0];
    const float* Wq = (const float*)d_in[1];
    const float* kw = (const float*)d_in[2];
    const float* vw = (const float*)d_in[3];
    const float* Wg = (const float*)d_in[4];
    const float* Wo = (const float*)d_in[5];
    float* out = (float*)d_out;

    __half *xh, *wq, *wg, *wo, *k, *vt, *qp, *ap;
    float* gate;
    GETSYMH(xh, g_x);
    GETSYMH(wq, g_wq); GETSYMH(wg, g_wg); GETSYMH(wo, g_wo);
    GETSYMH(k,  g_k);  GETSYMH(vt, g_vt);
    GETSYMH(qp, g_q);  GETSYMH(ap, g_a);
    { void* _p; cudaGetSymbolAddress(&_p, g_gate); gate = (float*)_p; }

    cudaFuncSetAttribute(qg_gemm,  cudaFuncAttributeMaxDynamicSharedMemorySize, 98304);
    cudaFuncSetAttribute(out_gemm, cudaFuncAttributeMaxDynamicSharedMemorySize, 98304);
    cudaFuncSetAttribute(attn_mma, cudaFuncAttributeMaxDynamicSharedMemorySize, 98304);

    // [0] merged pre-pass
    prep_kernel<<<dim3(8192, 6), 256>>>(x, xh, kw, k, Wq, wq, Wg, wg, Wo, wo, vw, vt);
    // [1] merged q + gate GEMM
    qg_gemm<<<dim3(16, 32, 2), 128, 98304>>>(xh, wq, qp, wg, gate);
    // [2] attention
    attn_mma<<<dim3(16, 16, 2), 256, 98304>>>(qp, k, vt, gate, ap);
    // [3] output GEMM
    out_gemm<<<dim3(16, 32), 128, 98304>>>(ap, wo, out);
}